// round 12
// baseline (speedup 1.0000x reference)
#include <cuda_runtime.h>
#include <cuda_bf16.h>
#include <cstdint>

// ---------------------------------------------------------------------------
// xLSTM_Model2: persistent row-parallel kernel.
// 64 CTAs x 256 threads; CTA b owns batch rows {2b, 2b+1} for the entire
// T=256 recurrence. All recurrent state in static SMEM. Weights streamed from
// L2 (10 MB total, L2-resident); each weight load is reused for both rows.
// ---------------------------------------------------------------------------

#define LNUM   3
#define HID    256
#define H2     128     // HID/2
#define NF     16
#define TF     17
#define BB     128
#define TT     256
#define LN_EPS 1e-5f
#define NT     256     // threads per CTA
#define GR     2       // batch rows per CTA
#define NWARP  (NT/32)

struct Ptrs {
    const float* __restrict__ params;      // [B,NF]
    const float* __restrict__ disp;        // [B,T]
    const float* __restrict__ embed_w;     // [TF,HID]
    const float* __restrict__ embed_b;     // [HID]
    const float* __restrict__ embed_g;     // [HID]
    const float* __restrict__ embed_beta;  // [HID]
    const float* __restrict__ skip_w;      // [TF,H2]
    const float* __restrict__ skip_b;      // [H2]
    const float* __restrict__ gates_w;     // [L,2H,4H]
    const float* __restrict__ gates_b;     // [L,4H]
    const float* __restrict__ inln_g;      // [L,HID]
    const float* __restrict__ inln_b;
    const float* __restrict__ hln_g;
    const float* __restrict__ hln_b;
    const float* __restrict__ sln_g;
    const float* __restrict__ sln_b;
    const float* __restrict__ aw1;         // [L,HID,HID]
    const float* __restrict__ ab1;         // [L,HID]
    const float* __restrict__ aw2;         // [L,HID,1]
    const float* __restrict__ ab2;         // [L,1]
    const float* __restrict__ rw1;         // [L,HID,2H]
    const float* __restrict__ rb1;         // [L,2H]
    const float* __restrict__ rw2;         // [L,2H,HID]
    const float* __restrict__ rb2;         // [L,HID]
    const float* __restrict__ rln_g;       // [L,HID]
    const float* __restrict__ rln_b;
    const float* __restrict__ ow1;         // [HID+H2, H2]
    const float* __restrict__ ob1;         // [H2]
    const float* __restrict__ oln_g;       // [H2]
    const float* __restrict__ oln_b;       // [H2]
    const float* __restrict__ ow2;         // [H2,1]
    const float* __restrict__ ob2;         // [1]
    float* __restrict__ out;               // [B,T]
};

__device__ __forceinline__ float sigmoidf_(float x) {
    return 1.0f / (1.0f + expf(-x));
}

__device__ __forceinline__ void fma4(float4& a, float s, const float4 w) {
    a.x += s * w.x; a.y += s * w.y; a.z += s * w.z; a.w += s * w.w;
}

// Block-wide sum of NV values across all NT threads; result broadcast to all.
template <int NV>
__device__ __forceinline__ void blk_reduce(float* v, float (*s_red)[8], float* s_bc,
                                           int tid, int lane, int warp) {
#pragma unroll
    for (int i = 0; i < NV; i++) {
        float x = v[i];
#pragma unroll
        for (int o = 16; o > 0; o >>= 1) x += __shfl_xor_sync(0xffffffffu, x, o);
        if (lane == 0) s_red[warp][i] = x;
    }
    __syncthreads();
    if (tid == 0) {
#pragma unroll
        for (int i = 0; i < NV; i++) {
            float s = s_red[0][i];
#pragma unroll
            for (int w = 1; w < NWARP; w++) s += s_red[w][i];
            s_bc[i] = s;
        }
    }
    __syncthreads();
#pragma unroll
    for (int i = 0; i < NV; i++) v[i] = s_bc[i];
}

__global__ void __launch_bounds__(NT)
xlstm_kernel(Ptrs p) {
    __shared__ __align__(16) float s_x[GR][HID];          // layer input / output
    __shared__ __align__(16) float s_h[GR][LNUM][HID];    // hidden state
    __shared__ __align__(16) float s_c[GR][LNUM][HID];    // cell state
    __shared__ __align__(16) float s_in[GR][2 * HID];     // GEMV input ([xn|hn] / t1)
    __shared__ __align__(16) float s_out[GR][4 * HID];    // gates pre-activation
    __shared__ __align__(16) float s_skip[GR][H2];
    __shared__ float s_xt[GR][TF];
    __shared__ float s_red[NWARP][8];
    __shared__ float s_bc[8];

    const int tid  = threadIdx.x;
    const int lane = tid & 31;
    const int warp = tid >> 5;
    const int r0   = blockIdx.x * GR;
    const float invH  = 1.0f / (float)HID;
    const float invH2 = 1.0f / (float)H2;

    // init recurrent state
#pragma unroll
    for (int r = 0; r < GR; r++)
#pragma unroll
        for (int l = 0; l < LNUM; l++) {
            s_h[r][l][tid] = 0.0f;
            s_c[r][l][tid] = 0.0f;
        }
    __syncthreads();

    for (int t = 0; t < TT; t++) {
        // ------- build xt = [disp_t, params] -------
        if (tid < TF) {
#pragma unroll
            for (int r = 0; r < GR; r++)
                s_xt[r][tid] = (tid == 0) ? p.disp[(r0 + r) * TT + t]
                                          : p.params[(r0 + r) * NF + (tid - 1)];
        }
        __syncthreads();

        // ------- embed (all 256 cols) + skip (first 128 threads) -------
        float e0 = p.embed_b[tid], e1 = e0;
#pragma unroll
        for (int k = 0; k < TF; k++) {
            float w = p.embed_w[k * HID + tid];
            e0 += s_xt[0][k] * w;
            e1 += s_xt[1][k] * w;
        }
        if (tid < H2) {
            float sk0 = p.skip_b[tid], sk1 = sk0;
#pragma unroll
            for (int k = 0; k < TF; k++) {
                float w = p.skip_w[k * H2 + tid];
                sk0 += s_xt[0][k] * w;
                sk1 += s_xt[1][k] * w;
            }
            s_skip[0][tid] = fmaxf(sk0, 0.0f);
            s_skip[1][tid] = fmaxf(sk1, 0.0f);
        }
        {
            float red[4] = { e0, e0 * e0, e1, e1 * e1 };
            blk_reduce<4>(red, s_red, s_bc, tid, lane, warp);
            float gv = p.embed_g[tid], bv = p.embed_beta[tid];
            float mu  = red[0] * invH;
            float var = red[1] * invH - mu * mu;
            float rs  = rsqrtf(var + LN_EPS);
            s_x[0][tid] = fmaxf((e0 - mu) * rs * gv + bv, 0.0f);
            mu  = red[2] * invH;
            var = red[3] * invH - mu * mu;
            rs  = rsqrtf(var + LN_EPS);
            s_x[1][tid] = fmaxf((e1 - mu) * rs * gv + bv, 0.0f);
        }
        __syncthreads();

        // ------- layers -------
#pragma unroll 1
        for (int l = 0; l < LNUM; l++) {
            float resid0, resid1, hkeep0, hkeep1;
            // LN(x) and LN(h) -> s_in = [xn | hn]
            {
                float xv0 = s_x[0][tid], xv1 = s_x[1][tid];
                float hv0 = s_h[0][l][tid], hv1 = s_h[1][l][tid];
                resid0 = xv0; resid1 = xv1;
                float red[8] = { xv0, xv0 * xv0, xv1, xv1 * xv1,
                                 hv0, hv0 * hv0, hv1, hv1 * hv1 };
                blk_reduce<8>(red, s_red, s_bc, tid, lane, warp);
                float igv = p.inln_g[l * HID + tid], ibv = p.inln_b[l * HID + tid];
                float hgv = p.hln_g[l * HID + tid],  hbv = p.hln_b[l * HID + tid];
                float mu, var, rs;
                mu = red[0] * invH; var = red[1] * invH - mu * mu; rs = rsqrtf(var + LN_EPS);
                s_in[0][tid] = (xv0 - mu) * rs * igv + ibv;
                mu = red[2] * invH; var = red[3] * invH - mu * mu; rs = rsqrtf(var + LN_EPS);
                s_in[1][tid] = (xv1 - mu) * rs * igv + ibv;
                mu = red[4] * invH; var = red[5] * invH - mu * mu; rs = rsqrtf(var + LN_EPS);
                s_in[0][HID + tid] = (hv0 - mu) * rs * hgv + hbv;
                mu = red[6] * invH; var = red[7] * invH - mu * mu; rs = rsqrtf(var + LN_EPS);
                s_in[1][HID + tid] = (hv1 - mu) * rs * hgv + hbv;
            }
            __syncthreads();

            // gates GEMV: [512] x [512,1024]; thread owns cols 4t..4t+3, both rows
            {
                float4 g0 = make_float4(0.f, 0.f, 0.f, 0.f), g1 = g0;
                const float* Wg = p.gates_w + (size_t)l * (2 * HID) * (4 * HID) + (tid << 2);
#pragma unroll 2
                for (int k = 0; k < 2 * HID; k += 4) {
                    float4 a0 = *reinterpret_cast<const float4*>(&s_in[0][k]);
                    float4 a1 = *reinterpret_cast<const float4*>(&s_in[1][k]);
                    const float* wp = Wg + (size_t)k * (4 * HID);
                    float4 w0 = *reinterpret_cast<const float4*>(wp);
                    float4 w1 = *reinterpret_cast<const float4*>(wp + 4 * HID);
                    float4 w2 = *reinterpret_cast<const float4*>(wp + 8 * HID);
                    float4 w3 = *reinterpret_cast<const float4*>(wp + 12 * HID);
                    fma4(g0, a0.x, w0); fma4(g0, a0.y, w1); fma4(g0, a0.z, w2); fma4(g0, a0.w, w3);
                    fma4(g1, a1.x, w0); fma4(g1, a1.y, w1); fma4(g1, a1.z, w2); fma4(g1, a1.w, w3);
                }
                float4 b4 = *reinterpret_cast<const float4*>(&p.gates_b[l * 4 * HID + (tid << 2)]);
                g0.x += b4.x; g0.y += b4.y; g0.z += b4.z; g0.w += b4.w;
                g1.x += b4.x; g1.y += b4.y; g1.z += b4.z; g1.w += b4.w;
                *reinterpret_cast<float4*>(&s_out[0][tid << 2]) = g0;
                *reinterpret_cast<float4*>(&s_out[1][tid << 2]) = g1;
            }

            // attention gate: imp = sigmoid(tanh(c @ aw1 + ab1) @ aw2 + ab2)
            float imp0, imp1;
            {
                const float* Wa = p.aw1 + (size_t)l * HID * HID + tid;
                float a0 = p.ab1[l * HID + tid], a1 = a0;
#pragma unroll 8
                for (int k = 0; k < HID; k++) {
                    float w = Wa[(size_t)k * HID];
                    a0 += s_c[0][l][k] * w;
                    a1 += s_c[1][l][k] * w;
                }
                float w2v = p.aw2[l * HID + tid];
                float red[2] = { tanhf(a0) * w2v, tanhf(a1) * w2v };
                blk_reduce<2>(red, s_red, s_bc, tid, lane, warp);  // also publishes s_out
                float ab2v = p.ab2[l];
                imp0 = sigmoidf_(red[0] + ab2v);
                imp1 = sigmoidf_(red[1] + ab2v);
            }

            // c/h update with LN
            {
                float iv0 = sigmoidf_(s_out[0][tid]);
                float fv0 = sigmoidf_(s_out[0][HID + tid]);
                float gv0 = tanhf(s_out[0][2 * HID + tid]);
                float ov0 = sigmoidf_(s_out[0][3 * HID + tid]);
                float iv1 = sigmoidf_(s_out[1][tid]);
                float fv1 = sigmoidf_(s_out[1][HID + tid]);
                float gv1 = tanhf(s_out[1][2 * HID + tid]);
                float ov1 = sigmoidf_(s_out[1][3 * HID + tid]);
                float cp0 = (fv0 * s_c[0][l][tid] + iv0 * gv0) * imp0;
                float cp1 = (fv1 * s_c[1][l][tid] + iv1 * gv1) * imp1;
                float red[4] = { cp0, cp0 * cp0, cp1, cp1 * cp1 };
                blk_reduce<4>(red, s_red, s_bc, tid, lane, warp);
                float sg = p.sln_g[l * HID + tid], sb = p.sln_b[l * HID + tid];
                float mu, var, rs, cn;
                mu = red[0] * invH; var = red[1] * invH - mu * mu; rs = rsqrtf(var + LN_EPS);
                cn = (cp0 - mu) * rs * sg + sb;
                s_c[0][l][tid] = cn;
                hkeep0 = ov0 * tanhf(cn);
                s_h[0][l][tid] = hkeep0;
                s_x[0][tid] = hkeep0;
                mu = red[2] * invH; var = red[3] * invH - mu * mu; rs = rsqrtf(var + LN_EPS);
                cn = (cp1 - mu) * rs * sg + sb;
                s_c[1][l][tid] = cn;
                hkeep1 = ov1 * tanhf(cn);
                s_h[1][l][tid] = hkeep1;
                s_x[1][tid] = hkeep1;
            }
            __syncthreads();

            // residual block GEMV 1: t1 = relu(x @ rw1 + rb1); thread owns cols 2t,2t+1
            {
                const float* W1 = p.rw1 + (size_t)l * HID * (2 * HID) + (tid << 1);
                float2 b2 = *reinterpret_cast<const float2*>(&p.rb1[l * 2 * HID + (tid << 1)]);
                float2 t0 = b2, t1 = b2;
#pragma unroll 4
                for (int k = 0; k < HID; k++) {
                    float2 w = *reinterpret_cast<const float2*>(&W1[(size_t)k * 2 * HID]);
                    float a0 = s_x[0][k], a1 = s_x[1][k];
                    t0.x += a0 * w.x; t0.y += a0 * w.y;
                    t1.x += a1 * w.x; t1.y += a1 * w.y;
                }
                s_in[0][tid << 1]       = fmaxf(t0.x, 0.0f);
                s_in[0][(tid << 1) + 1] = fmaxf(t0.y, 0.0f);
                s_in[1][tid << 1]       = fmaxf(t1.x, 0.0f);
                s_in[1][(tid << 1) + 1] = fmaxf(t1.y, 0.0f);
            }
            __syncthreads();

            // residual block GEMV 2 + LN + residual
            {
                const float* W2 = p.rw2 + (size_t)l * (2 * HID) * HID + tid;
                float a0 = p.rb2[l * HID + tid], a1 = a0;
#pragma unroll 8
                for (int m = 0; m < 2 * HID; m++) {
                    float w = W2[(size_t)m * HID];
                    a0 += s_in[0][m] * w;
                    a1 += s_in[1][m] * w;
                }
                float v0 = a0 + hkeep0, v1 = a1 + hkeep1;
                float red[4] = { v0, v0 * v0, v1, v1 * v1 };
                blk_reduce<4>(red, s_red, s_bc, tid, lane, warp);
                float rg = p.rln_g[l * HID + tid], rb = p.rln_b[l * HID + tid];
                float mu, var, rs;
                mu = red[0] * invH; var = red[1] * invH - mu * mu; rs = rsqrtf(var + LN_EPS);
                s_x[0][tid] = (v0 - mu) * rs * rg + rb + resid0;
                mu = red[2] * invH; var = red[3] * invH - mu * mu; rs = rsqrtf(var + LN_EPS);
                s_x[1][tid] = (v1 - mu) * rs * rg + rb + resid1;
            }
            __syncthreads();
        }

        // ------- output head: half-block per row -------
        {
            const int j  = tid & (H2 - 1);
            const int rr = tid >> 7;
            float acc = p.ob1[j];
#pragma unroll 4
            for (int k = 0; k < HID; k++)
                acc += s_x[rr][k] * p.ow1[k * H2 + j];
#pragma unroll 4
            for (int k = 0; k < H2; k++)
                acc += s_skip[rr][k] * p.ow1[(HID + k) * H2 + j];

            float red[4] = { 0.f, 0.f, 0.f, 0.f };
            red[2 * rr]     = acc;
            red[2 * rr + 1] = acc * acc;
            blk_reduce<4>(red, s_red, s_bc, tid, lane, warp);
            float mu  = red[2 * rr] * invH2;
            float var = red[2 * rr + 1] * invH2 - mu * mu;
            float rs  = rsqrtf(var + LN_EPS);
            float z = fmaxf((acc - mu) * rs * p.oln_g[j] + p.oln_b[j], 0.0f);

            float red2[2] = { 0.f, 0.f };
            red2[rr] = z * p.ow2[j];
            blk_reduce<2>(red2, s_red, s_bc, tid, lane, warp);
            if (tid == 0)   p.out[(size_t)r0 * TT + t]       = red2[0] + p.ob2[0];
            if (tid == 128) p.out[(size_t)(r0 + 1) * TT + t] = red2[1] + p.ob2[0];
        }
        __syncthreads();
    }
}

extern "C" void kernel_launch(void* const* d_in, const int* in_sizes, int n_in,
                              void* d_out, int out_size) {
    Ptrs p;
    p.params     = (const float*)d_in[0];
    p.disp       = (const float*)d_in[1];
    p.embed_w    = (const float*)d_in[2];
    p.embed_b    = (const float*)d_in[3];
    p.embed_g    = (const float*)d_in[4];
    p.embed_beta = (const float*)d_in[5];
    p.skip_w     = (const float*)d_in[6];
    p.skip_b     = (const float*)d_in[7];
    p.gates_w    = (const float*)d_in[8];
    p.gates_b    = (const float*)d_in[9];
    p.inln_g     = (const float*)d_in[10];
    p.inln_b     = (const float*)d_in[11];
    p.hln_g      = (const float*)d_in[12];
    p.hln_b      = (const float*)d_in[13];
    p.sln_g      = (const float*)d_in[14];
    p.sln_b      = (const float*)d_in[15];
    p.aw1        = (const float*)d_in[16];
    p.ab1        = (const float*)d_in[17];
    p.aw2        = (const float*)d_in[18];
    p.ab2        = (const float*)d_in[19];
    p.rw1        = (const float*)d_in[20];
    p.rb1        = (const float*)d_in[21];
    p.rw2        = (const float*)d_in[22];
    p.rb2        = (const float*)d_in[23];
    p.rln_g      = (const float*)d_in[24];
    p.rln_b      = (const float*)d_in[25];
    p.ow1        = (const float*)d_in[26];
    p.ob1        = (const float*)d_in[27];
    p.oln_g      = (const float*)d_in[28];
    p.oln_b      = (const float*)d_in[29];
    p.ow2        = (const float*)d_in[30];
    p.ob2        = (const float*)d_in[31];
    p.out        = (float*)d_out;

    xlstm_kernel<<<BB / GR, NT>>>(p);
}

// round 13
// speedup vs baseline: 2.2439x; 2.2439x over previous
#include <cuda_runtime.h>
#include <cstdint>

// ---------------------------------------------------------------------------
// xLSTM_Model2 — cluster-sliced persistent kernel.
// 32 clusters x 4 CTAs (128 CTAs, 256 thr). Each cluster owns 4 batch rows for
// the whole T=256 recurrence. Within a cluster, CTA rank r computes the r-th
// quarter of every GEMV's output columns (weights loaded once, reused across
// the 4 rows in registers), and broadcasts its slice to all peers via DSMEM
// (mapa + st.shared::cluster.v4) with barrier.cluster syncs. Elementwise /
// LayerNorm work is done redundantly on replicated state. Inner products use
// packed fma.rn.f32x2 (rows paired).
// ---------------------------------------------------------------------------

#define LNUM   3
#define HID    256
#define H2     128
#define NF     16
#define TF     17
#define BB     128
#define TT     256
#define LN_EPS 1e-5f
#define NT     256
#define NWARP  8
#define CSZ    4      // cluster size
#define GRW    4      // rows per cluster

typedef unsigned long long u64;

struct Ptrs {
    const float* __restrict__ params;
    const float* __restrict__ disp;
    const float* __restrict__ embed_w;
    const float* __restrict__ embed_b;
    const float* __restrict__ embed_g;
    const float* __restrict__ embed_beta;
    const float* __restrict__ skip_w;
    const float* __restrict__ skip_b;
    const float* __restrict__ gates_w;
    const float* __restrict__ gates_b;
    const float* __restrict__ inln_g;
    const float* __restrict__ inln_b;
    const float* __restrict__ hln_g;
    const float* __restrict__ hln_b;
    const float* __restrict__ sln_g;
    const float* __restrict__ sln_b;
    const float* __restrict__ aw1;
    const float* __restrict__ ab1;
    const float* __restrict__ aw2;
    const float* __restrict__ ab2;
    const float* __restrict__ rw1;
    const float* __restrict__ rb1;
    const float* __restrict__ rw2;
    const float* __restrict__ rb2;
    const float* __restrict__ rln_g;
    const float* __restrict__ rln_b;
    const float* __restrict__ ow1;
    const float* __restrict__ ob1;
    const float* __restrict__ oln_g;
    const float* __restrict__ oln_b;
    const float* __restrict__ ow2;
    const float* __restrict__ ob2;
    float* __restrict__ out;
};

// All activation buffers row-minor: buf[dim] is a float4 holding rows 0..3.
struct Smem {
    float4 x[HID];          // layer input/output (rows 0..3)
    float4 skip[H2];        // MUST follow x: head GEMV reads [x | skip] as 384
    float4 h[LNUM][HID];
    float4 c[LNUM][HID];
    float4 gin[2 * HID];    // [xn | hn]; reused as r2 pre-LN buffer
    float4 g4[4 * HID];     // assembled gate pre-activations
    float4 t1[2 * HID];     // residual hidden
    float4 hd[H2];          // head pre-LN
    float4 part[1024];      // k-partition partials (16KB, shared by all GEMVs)
    float4 xt[TF];
    float4 attnp[CSZ];      // per-rank attention dot partials (per row)
    float  red[NWARP][16];
    float  bc[16];
};

__device__ __forceinline__ uint32_t sm2u(const void* p) {
    uint32_t a;
    asm("{ .reg .u64 t; cvta.to.shared.u64 t, %1; cvt.u32.u64 %0, t; }"
        : "=r"(a) : "l"(p));
    return a;
}
__device__ __forceinline__ uint32_t ctarank() {
    uint32_t r; asm("mov.u32 %0, %%cluster_ctarank;" : "=r"(r)); return r;
}
#define CLUSTER_SYNC() do { \
    asm volatile("barrier.cluster.arrive.aligned;" ::: "memory"); \
    asm volatile("barrier.cluster.wait.aligned;"   ::: "memory"); \
} while (0)

__device__ __forceinline__ u64 fma2(u64 a, u64 b, u64 c) {
    u64 d;
    asm("fma.rn.f32x2 %0, %1, %2, %3;" : "=l"(d) : "l"(a), "l"(b), "l"(c));
    return d;
}
__device__ __forceinline__ u64 rep2(float x) {
    u64 d; unsigned xb = __float_as_uint(x);
    asm("mov.b64 %0, {%1, %1};" : "=l"(d) : "r"(xb));
    return d;
}
__device__ __forceinline__ float2 unpk(u64 v) {
    unsigned lo, hi;
    asm("mov.b64 {%0, %1}, %2;" : "=r"(lo), "=r"(hi) : "l"(v));
    return make_float2(__uint_as_float(lo), __uint_as_float(hi));
}

// Broadcast one float4 into every cluster CTA's SMEM at the same offset.
__device__ __forceinline__ void push_all(const void* lptr, float4 v) {
    uint32_t la = sm2u(lptr);
#pragma unroll
    for (int pr = 0; pr < CSZ; pr++) {
        uint32_t ra;
        asm("mapa.shared::cluster.u32 %0, %1, %2;" : "=r"(ra) : "r"(la), "r"(pr));
        asm volatile("st.shared::cluster.v4.f32 [%0], {%1, %2, %3, %4};"
                     :: "r"(ra), "f"(v.x), "f"(v.y), "f"(v.z), "f"(v.w)
                     : "memory");
    }
}

__device__ __forceinline__ float sigmoidf_(float x) {
    return 1.0f / (1.0f + expf(-x));
}

// Output-stationary sliced GEMV. W: k-major rows (stride WS), pre-offset to
// this CTA's column slice. act[dim] = float4 (4 rows). Thread = (col-group
// cg = tid & (CG-1), k-partition kp = tid / CG), KLEN k's each. Results go
// to part[kp*(4CG) + col] as float4 over rows.
template <int CG, int KP, int KLEN, int WS>
__device__ __forceinline__ void gemv4(const float* __restrict__ W,
                                      const float4* __restrict__ act,
                                      float4* __restrict__ part, int tid) {
    const int cg = tid & (CG - 1);
    const int kp = tid / CG;
    const float* wp = W + (size_t)(kp * KLEN) * WS + (cg << 2);
    const ulonglong2* ap = reinterpret_cast<const ulonglong2*>(act + kp * KLEN);
    u64 a01[4] = {0ull, 0ull, 0ull, 0ull};
    u64 a23[4] = {0ull, 0ull, 0ull, 0ull};
#pragma unroll 4
    for (int k = 0; k < KLEN; k++) {
        float4 w = *reinterpret_cast<const float4*>(wp + (size_t)k * WS);
        ulonglong2 av = ap[k];              // rows (0,1) and (2,3) packed
        u64 w0 = rep2(w.x), w1 = rep2(w.y), w2 = rep2(w.z), w3 = rep2(w.w);
        a01[0] = fma2(w0, av.x, a01[0]);  a23[0] = fma2(w0, av.y, a23[0]);
        a01[1] = fma2(w1, av.x, a01[1]);  a23[1] = fma2(w1, av.y, a23[1]);
        a01[2] = fma2(w2, av.x, a01[2]);  a23[2] = fma2(w2, av.y, a23[2]);
        a01[3] = fma2(w3, av.x, a01[3]);  a23[3] = fma2(w3, av.y, a23[3]);
    }
#pragma unroll
    for (int cc = 0; cc < 4; cc++) {
        float2 lo = unpk(a01[cc]);
        float2 hi = unpk(a23[cc]);
        part[kp * (CG * 4) + (cg << 2) + cc] = make_float4(lo.x, lo.y, hi.x, hi.y);
    }
}

template <int NC, int KP>
__device__ __forceinline__ float4 combine(const float4* __restrict__ part, int j) {
    float4 s = part[j];
#pragma unroll
    for (int kp = 1; kp < KP; kp++) {
        float4 q = part[kp * NC + j];
        s.x += q.x; s.y += q.y; s.z += q.z; s.w += q.w;
    }
    return s;
}

template <int NV>
__device__ __forceinline__ void blk_reduce(float* v, Smem* s, int tid, int lane, int warp) {
#pragma unroll
    for (int i = 0; i < NV; i++) {
        float x = v[i];
#pragma unroll
        for (int o = 16; o > 0; o >>= 1) x += __shfl_xor_sync(0xffffffffu, x, o);
        if (lane == 0) s->red[warp][i] = x;
    }
    __syncthreads();
    if (tid == 0) {
#pragma unroll
        for (int i = 0; i < NV; i++) {
            float acc = s->red[0][i];
#pragma unroll
            for (int w = 1; w < NWARP; w++) acc += s->red[w][i];
            s->bc[i] = acc;
        }
    }
    __syncthreads();
#pragma unroll
    for (int i = 0; i < NV; i++) v[i] = s->bc[i];
}

__global__ void __launch_bounds__(NT) __cluster_dims__(CSZ, 1, 1)
xlstm_kernel(Ptrs p) {
    extern __shared__ char smem_raw[];
    Smem* s = reinterpret_cast<Smem*>(smem_raw);

    const int tid  = threadIdx.x;
    const int lane = tid & 31;
    const int warp = tid >> 5;
    const uint32_t rk = ctarank();
    const int row0 = (blockIdx.x & ~(CSZ - 1));   // = cluster_id * 4 (GRW rows)
    const float invH  = 1.0f / (float)HID;
    const float invH2 = 1.0f / (float)H2;
    const float4 z4 = make_float4(0.f, 0.f, 0.f, 0.f);

#pragma unroll
    for (int l = 0; l < LNUM; l++) {
        s->h[l][tid] = z4;
        s->c[l][tid] = z4;
    }
    __syncthreads();

    for (int t = 0; t < TT; t++) {
        // ---- xt = [disp_t | params], replicated, row-minor ----
        if (tid < TF * 4) {
            int j = tid >> 2, rr = tid & 3;
            float v = (j == 0) ? p.disp[(size_t)(row0 + rr) * TT + t]
                               : p.params[(size_t)(row0 + rr) * NF + (j - 1)];
            reinterpret_cast<float*>(&s->xt[j])[rr] = v;
        }
        __syncthreads();

        // ---- embed (redundant, col = tid) + skip (threads < 128) ----
        {
            float eb = p.embed_b[tid];
            float4 e = make_float4(eb, eb, eb, eb);
#pragma unroll
            for (int k = 0; k < TF; k++) {
                float w = p.embed_w[k * HID + tid];
                float4 xt = s->xt[k];
                e.x += xt.x * w; e.y += xt.y * w; e.z += xt.z * w; e.w += xt.w * w;
            }
            if (tid < H2) {
                float sb = p.skip_b[tid];
                float4 sk = make_float4(sb, sb, sb, sb);
#pragma unroll
                for (int k = 0; k < TF; k++) {
                    float w = p.skip_w[k * H2 + tid];
                    float4 xt = s->xt[k];
                    sk.x += xt.x * w; sk.y += xt.y * w; sk.z += xt.z * w; sk.w += xt.w * w;
                }
                sk.x = fmaxf(sk.x, 0.f); sk.y = fmaxf(sk.y, 0.f);
                sk.z = fmaxf(sk.z, 0.f); sk.w = fmaxf(sk.w, 0.f);
                s->skip[tid] = sk;
            }
            float r8[8] = { e.x, e.x * e.x, e.y, e.y * e.y,
                            e.z, e.z * e.z, e.w, e.w * e.w };
            blk_reduce<8>(r8, s, tid, lane, warp);
            float g = p.embed_g[tid], b = p.embed_beta[tid];
            float4 xo;
            float mu, var, rs;
            mu = r8[0] * invH; var = r8[1] * invH - mu * mu; rs = rsqrtf(var + LN_EPS);
            xo.x = fmaxf((e.x - mu) * rs * g + b, 0.f);
            mu = r8[2] * invH; var = r8[3] * invH - mu * mu; rs = rsqrtf(var + LN_EPS);
            xo.y = fmaxf((e.y - mu) * rs * g + b, 0.f);
            mu = r8[4] * invH; var = r8[5] * invH - mu * mu; rs = rsqrtf(var + LN_EPS);
            xo.z = fmaxf((e.z - mu) * rs * g + b, 0.f);
            mu = r8[6] * invH; var = r8[7] * invH - mu * mu; rs = rsqrtf(var + LN_EPS);
            xo.w = fmaxf((e.w - mu) * rs * g + b, 0.f);
            s->x[tid] = xo;
        }
        __syncthreads();

        // ---- layers ----
#pragma unroll 1
        for (int l = 0; l < LNUM; l++) {
            float4 resid;
            // LN(x), LN(h) -> gin = [xn | hn]
            {
                float4 xv = s->x[tid];
                float4 hv = s->h[l][tid];
                resid = xv;
                float r16[16] = { xv.x, xv.x * xv.x, xv.y, xv.y * xv.y,
                                  xv.z, xv.z * xv.z, xv.w, xv.w * xv.w,
                                  hv.x, hv.x * hv.x, hv.y, hv.y * hv.y,
                                  hv.z, hv.z * hv.z, hv.w, hv.w * hv.w };
                blk_reduce<16>(r16, s, tid, lane, warp);
                float ig = p.inln_g[l * HID + tid], ib = p.inln_b[l * HID + tid];
                float hg = p.hln_g[l * HID + tid],  hb = p.hln_b[l * HID + tid];
                float4 xn, hn;
                float mu, var, rs;
                mu = r16[0] * invH; var = r16[1] * invH - mu * mu; rs = rsqrtf(var + LN_EPS);
                xn.x = (xv.x - mu) * rs * ig + ib;
                mu = r16[2] * invH; var = r16[3] * invH - mu * mu; rs = rsqrtf(var + LN_EPS);
                xn.y = (xv.y - mu) * rs * ig + ib;
                mu = r16[4] * invH; var = r16[5] * invH - mu * mu; rs = rsqrtf(var + LN_EPS);
                xn.z = (xv.z - mu) * rs * ig + ib;
                mu = r16[6] * invH; var = r16[7] * invH - mu * mu; rs = rsqrtf(var + LN_EPS);
                xn.w = (xv.w - mu) * rs * ig + ib;
                mu = r16[8] * invH; var = r16[9] * invH - mu * mu; rs = rsqrtf(var + LN_EPS);
                hn.x = (hv.x - mu) * rs * hg + hb;
                mu = r16[10] * invH; var = r16[11] * invH - mu * mu; rs = rsqrtf(var + LN_EPS);
                hn.y = (hv.y - mu) * rs * hg + hb;
                mu = r16[12] * invH; var = r16[13] * invH - mu * mu; rs = rsqrtf(var + LN_EPS);
                hn.z = (hv.z - mu) * rs * hg + hb;
                mu = r16[14] * invH; var = r16[15] * invH - mu * mu; rs = rsqrtf(var + LN_EPS);
                hn.w = (hv.w - mu) * rs * hg + hb;
                s->gin[tid]       = xn;
                s->gin[HID + tid] = hn;
            }
            __syncthreads();

            // gates GEMV slice: cols [rk*256, rk*256+256) of 1024, k=512
            gemv4<64, 4, 128, 4 * HID>(
                p.gates_w + (size_t)l * (2 * HID) * (4 * HID) + rk * 256,
                s->gin, s->part, tid);
            __syncthreads();
            {
                float4 g = combine<256, 4>(s->part, tid);
                float bb = p.gates_b[l * 4 * HID + rk * 256 + tid];
                g.x += bb; g.y += bb; g.z += bb; g.w += bb;
                push_all(&s->g4[rk * 256 + tid], g);
            }
            __syncthreads();   // s->part reuse

            // attention GEMV slice (old c): cols [rk*64, +64) of 256
            gemv4<16, 16, 16, HID>(
                p.aw1 + (size_t)l * HID * HID + rk * 64,
                s->c[l], s->part, tid);
            __syncthreads();
            {
                float r4[4] = {0.f, 0.f, 0.f, 0.f};
                if (tid < 64) {
                    float4 a = combine<64, 16>(s->part, tid);
                    float ab = p.ab1[l * HID + rk * 64 + tid];
                    float w2 = p.aw2[l * HID + rk * 64 + tid];
                    r4[0] = tanhf(a.x + ab) * w2;
                    r4[1] = tanhf(a.y + ab) * w2;
                    r4[2] = tanhf(a.z + ab) * w2;
                    r4[3] = tanhf(a.w + ab) * w2;
                }
                blk_reduce<4>(r4, s, tid, lane, warp);
                if (tid == 0)
                    push_all(&s->attnp[rk], make_float4(r4[0], r4[1], r4[2], r4[3]));
            }
            CLUSTER_SYNC();   // g4 + attnp fully assembled in every CTA

            // c/h update (redundant, col = tid)
            {
                float4 pa = s->attnp[0], pb = s->attnp[1],
                       pc = s->attnp[2], pd = s->attnp[3];
                float ab2v = p.ab2[l];
                float4 imp;
                imp.x = sigmoidf_(pa.x + pb.x + pc.x + pd.x + ab2v);
                imp.y = sigmoidf_(pa.y + pb.y + pc.y + pd.y + ab2v);
                imp.z = sigmoidf_(pa.z + pb.z + pc.z + pd.z + ab2v);
                imp.w = sigmoidf_(pa.w + pb.w + pc.w + pd.w + ab2v);
                float4 gi = s->g4[tid];
                float4 gf = s->g4[HID + tid];
                float4 gg = s->g4[2 * HID + tid];
                float4 go = s->g4[3 * HID + tid];
                float4 co = s->c[l][tid];
                float4 cp;
                cp.x = (sigmoidf_(gf.x) * co.x + sigmoidf_(gi.x) * tanhf(gg.x)) * imp.x;
                cp.y = (sigmoidf_(gf.y) * co.y + sigmoidf_(gi.y) * tanhf(gg.y)) * imp.y;
                cp.z = (sigmoidf_(gf.z) * co.z + sigmoidf_(gi.z) * tanhf(gg.z)) * imp.z;
                cp.w = (sigmoidf_(gf.w) * co.w + sigmoidf_(gi.w) * tanhf(gg.w)) * imp.w;
                float r8[8] = { cp.x, cp.x * cp.x, cp.y, cp.y * cp.y,
                                cp.z, cp.z * cp.z, cp.w, cp.w * cp.w };
                blk_reduce<8>(r8, s, tid, lane, warp);
                float sg = p.sln_g[l * HID + tid], sb = p.sln_b[l * HID + tid];
                float4 cn, hv;
                float mu, var, rs;
                mu = r8[0] * invH; var = r8[1] * invH - mu * mu; rs = rsqrtf(var + LN_EPS);
                cn.x = (cp.x - mu) * rs * sg + sb;  hv.x = sigmoidf_(go.x) * tanhf(cn.x);
                mu = r8[2] * invH; var = r8[3] * invH - mu * mu; rs = rsqrtf(var + LN_EPS);
                cn.y = (cp.y - mu) * rs * sg + sb;  hv.y = sigmoidf_(go.y) * tanhf(cn.y);
                mu = r8[4] * invH; var = r8[5] * invH - mu * mu; rs = rsqrtf(var + LN_EPS);
                cn.z = (cp.z - mu) * rs * sg + sb;  hv.z = sigmoidf_(go.z) * tanhf(cn.z);
                mu = r8[6] * invH; var = r8[7] * invH - mu * mu; rs = rsqrtf(var + LN_EPS);
                cn.w = (cp.w - mu) * rs * sg + sb;  hv.w = sigmoidf_(go.w) * tanhf(cn.w);
                s->c[l][tid] = cn;
                s->h[l][tid] = hv;
                s->x[tid]    = hv;
            }
            __syncthreads();

            // residual GEMV1 slice: cols [rk*128, +128) of 512, k=256
            gemv4<32, 8, 32, 2 * HID>(
                p.rw1 + (size_t)l * HID * (2 * HID) + rk * 128,
                s->x, s->part, tid);
            __syncthreads();
            if (tid < 128) {
                float4 v = combine<128, 8>(s->part, tid);
                float bb = p.rb1[l * 2 * HID + rk * 128 + tid];
                v.x = fmaxf(v.x + bb, 0.f); v.y = fmaxf(v.y + bb, 0.f);
                v.z = fmaxf(v.z + bb, 0.f); v.w = fmaxf(v.w + bb, 0.f);
                push_all(&s->t1[rk * 128 + tid], v);
            }
            CLUSTER_SYNC();   // t1 assembled

            // residual GEMV2 slice: cols [rk*64, +64) of 256, k=512
            gemv4<16, 16, 32, HID>(
                p.rw2 + (size_t)l * (2 * HID) * HID + rk * 64,
                s->t1, s->part, tid);
            __syncthreads();
            if (tid < 64) {
                float4 v = combine<64, 16>(s->part, tid);
                int gcol = rk * 64 + tid;
                float bb = p.rb2[l * HID + gcol];
                float4 xv = s->x[gcol];           // = h (pre r-LN)
                v.x += bb + xv.x; v.y += bb + xv.y;
                v.z += bb + xv.z; v.w += bb + xv.w;
                push_all(&s->gin[gcol], v);       // gin reused as pre-LN buffer
            }
            CLUSTER_SYNC();   // pre-LN vector assembled

            // r-LN + residual
            {
                float4 v = s->gin[tid];
                float r8[8] = { v.x, v.x * v.x, v.y, v.y * v.y,
                                v.z, v.z * v.z, v.w, v.w * v.w };
                blk_reduce<8>(r8, s, tid, lane, warp);
                float rg = p.rln_g[l * HID + tid], rb = p.rln_b[l * HID + tid];
                float4 xo;
                float mu, var, rs;
                mu = r8[0] * invH; var = r8[1] * invH - mu * mu; rs = rsqrtf(var + LN_EPS);
                xo.x = (v.x - mu) * rs * rg + rb + resid.x;
                mu = r8[2] * invH; var = r8[3] * invH - mu * mu; rs = rsqrtf(var + LN_EPS);
                xo.y = (v.y - mu) * rs * rg + rb + resid.y;
                mu = r8[4] * invH; var = r8[5] * invH - mu * mu; rs = rsqrtf(var + LN_EPS);
                xo.z = (v.z - mu) * rs * rg + rb + resid.z;
                mu = r8[6] * invH; var = r8[7] * invH - mu * mu; rs = rsqrtf(var + LN_EPS);
                xo.w = (v.w - mu) * rs * rg + rb + resid.w;
                s->x[tid] = xo;
            }
            __syncthreads();
        }

        // ---- output head ----
        // GEMV slice over y = [x | skip] (384), cols [rk*32, +32) of 128
        gemv4<8, 32, 12, H2>(p.ow1 + rk * 32, s->x, s->part, tid);
        __syncthreads();
        if (tid < 32) {
            float4 v = combine<32, 32>(s->part, tid);
            float bb = p.ob1[rk * 32 + tid];
            v.x += bb; v.y += bb; v.z += bb; v.w += bb;
            push_all(&s->hd[rk * 32 + tid], v);
        }
        CLUSTER_SYNC();   // hd assembled
        {
            float4 zv = z4;
            float r8[8] = {0.f, 0.f, 0.f, 0.f, 0.f, 0.f, 0.f, 0.f};
            if (tid < H2) {
                zv = s->hd[tid];
                r8[0] = zv.x; r8[1] = zv.x * zv.x;
                r8[2] = zv.y; r8[3] = zv.y * zv.y;
                r8[4] = zv.z; r8[5] = zv.z * zv.z;
                r8[6] = zv.w; r8[7] = zv.w * zv.w;
            }
            blk_reduce<8>(r8, s, tid, lane, warp);
            float r4[4] = {0.f, 0.f, 0.f, 0.f};
            if (tid < H2) {
                float og = p.oln_g[tid], ob = p.oln_b[tid];
                float w2 = p.ow2[tid];
                float mu, var, rs;
                mu = r8[0] * invH2; var = r8[1] * invH2 - mu * mu; rs = rsqrtf(var + LN_EPS);
                r4[0] = fmaxf((zv.x - mu) * rs * og + ob, 0.f) * w2;
                mu = r8[2] * invH2; var = r8[3] * invH2 - mu * mu; rs = rsqrtf(var + LN_EPS);
                r4[1] = fmaxf((zv.y - mu) * rs * og + ob, 0.f) * w2;
                mu = r8[4] * invH2; var = r8[5] * invH2 - mu * mu; rs = rsqrtf(var + LN_EPS);
                r4[2] = fmaxf((zv.z - mu) * rs * og + ob, 0.f) * w2;
                mu = r8[6] * invH2; var = r8[7] * invH2 - mu * mu; rs = rsqrtf(var + LN_EPS);
                r4[3] = fmaxf((zv.w - mu) * rs * og + ob, 0.f) * w2;
            }
            blk_reduce<4>(r4, s, tid, lane, warp);
            if (tid < 4)
                p.out[(size_t)(row0 + tid) * TT + t] = r4[tid] + p.ob2[0];
        }
        __syncthreads();
    }
}

extern "C" void kernel_launch(void* const* d_in, const int* in_sizes, int n_in,
                              void* d_out, int out_size) {
    Ptrs p;
    p.params     = (const float*)d_in[0];
    p.disp       = (const float*)d_in[1];
    p.embed_w    = (const float*)d_in[2];
    p.embed_b    = (const float*)d_in[3];
    p.embed_g    = (const float*)d_in[4];
    p.embed_beta = (const float*)d_in[5];
    p.skip_w     = (const float*)d_in[6];
    p.skip_b     = (const float*)d_in[7];
    p.gates_w    = (const float*)d_in[8];
    p.gates_b    = (const float*)d_in[9];
    p.inln_g     = (const float*)d_in[10];
    p.inln_b     = (const float*)d_in[11];
    p.hln_g      = (const float*)d_in[12];
    p.hln_b      = (const float*)d_in[13];
    p.sln_g      = (const float*)d_in[14];
    p.sln_b      = (const float*)d_in[15];
    p.aw1        = (const float*)d_in[16];
    p.ab1        = (const float*)d_in[17];
    p.aw2        = (const float*)d_in[18];
    p.ab2        = (const float*)d_in[19];
    p.rw1        = (const float*)d_in[20];
    p.rb1        = (const float*)d_in[21];
    p.rw2        = (const float*)d_in[22];
    p.rb2        = (const float*)d_in[23];
    p.rln_g      = (const float*)d_in[24];
    p.rln_b      = (const float*)d_in[25];
    p.ow1        = (const float*)d_in[26];
    p.ob1        = (const float*)d_in[27];
    p.oln_g      = (const float*)d_in[28];
    p.oln_b      = (const float*)d_in[29];
    p.ow2        = (const float*)d_in[30];
    p.ob2        = (const float*)d_in[31];
    p.out        = (float*)d_out;

    cudaFuncSetAttribute(xlstm_kernel,
                         cudaFuncAttributeMaxDynamicSharedMemorySize,
                         (int)sizeof(Smem));
    xlstm_kernel<<<BB, NT, sizeof(Smem)>>>(p);
}

// round 15
// speedup vs baseline: 2.6659x; 1.1881x over previous
#include <cuda_runtime.h>
#include <cstdint>

// ---------------------------------------------------------------------------
// xLSTM_Model2 — cluster-sliced persistent kernel, v2.
// 32 clusters x 4 CTAs (128 CTAs) x 512 threads. Cluster owns 4 batch rows for
// the whole T=256 recurrence. CTA rank r computes the r-th quarter of every
// GEMV's output columns (weights loaded once, reused across 4 rows via packed
// fma.rn.f32x2), broadcasts slices to peers via DSMEM + barrier.cluster.
// Elementwise/LN work is (col, row-pair) parallel across all 512 threads with
// rp-partitioned block reductions. Fast transcendentals (__expf-based).
// ---------------------------------------------------------------------------

#define LNUM   3
#define HID    256
#define H2     128
#define NF     16
#define TF     17
#define BB     128
#define TT     256
#define LN_EPS 1e-5f
#define NT     512
#define NWARP  16
#define CSZ    4

typedef unsigned long long u64;

struct Ptrs {
    const float* __restrict__ params;
    const float* __restrict__ disp;
    const float* __restrict__ embed_w;
    const float* __restrict__ embed_b;
    const float* __restrict__ embed_g;
    const float* __restrict__ embed_beta;
    const float* __restrict__ skip_w;
    const float* __restrict__ skip_b;
    const float* __restrict__ gates_w;
    const float* __restrict__ gates_b;
    const float* __restrict__ inln_g;
    const float* __restrict__ inln_b;
    const float* __restrict__ hln_g;
    const float* __restrict__ hln_b;
    const float* __restrict__ sln_g;
    const float* __restrict__ sln_b;
    const float* __restrict__ aw1;
    const float* __restrict__ ab1;
    const float* __restrict__ aw2;
    const float* __restrict__ ab2;
    const float* __restrict__ rw1;
    const float* __restrict__ rb1;
    const float* __restrict__ rw2;
    const float* __restrict__ rb2;
    const float* __restrict__ rln_g;
    const float* __restrict__ rln_b;
    const float* __restrict__ ow1;
    const float* __restrict__ ob1;
    const float* __restrict__ oln_g;
    const float* __restrict__ oln_b;
    const float* __restrict__ ow2;
    const float* __restrict__ ob2;
    float* __restrict__ out;
};

// Row-minor activations: buf[dim] = float4 of rows 0..3.
struct Smem {
    float4 x[HID];
    float4 skip[H2];        // MUST follow x: head GEMV reads [x | skip] as 384
    float4 h[LNUM][HID];
    float4 c[LNUM][HID];
    float4 gin[2 * HID];    // [xn | hn]; reused as r2 pre-LN buffer
    float4 g4[4 * HID];
    float4 t1[2 * HID];
    float4 hd[H2];
    float4 part[2048];      // k-partition partials (32KB)
    float4 xt[TF];
    float4 attnp[CSZ];
    float  red[NWARP][16];
    float  bc[16];
};

__device__ __forceinline__ uint32_t sm2u(const void* p) {
    uint32_t a;
    asm("{ .reg .u64 t; cvta.to.shared.u64 t, %1; cvt.u32.u64 %0, t; }"
        : "=r"(a) : "l"(p));
    return a;
}
__device__ __forceinline__ uint32_t ctarank() {
    uint32_t r; asm("mov.u32 %0, %%cluster_ctarank;" : "=r"(r)); return r;
}
#define CLUSTER_SYNC() do { \
    asm volatile("barrier.cluster.arrive.aligned;" ::: "memory"); \
    asm volatile("barrier.cluster.wait.aligned;"   ::: "memory"); \
} while (0)

__device__ __forceinline__ u64 fma2(u64 a, u64 b, u64 c) {
    u64 d;
    asm("fma.rn.f32x2 %0, %1, %2, %3;" : "=l"(d) : "l"(a), "l"(b), "l"(c));
    return d;
}
__device__ __forceinline__ u64 rep2(float x) {
    u64 d; unsigned xb = __float_as_uint(x);
    asm("mov.b64 %0, {%1, %1};" : "=l"(d) : "r"(xb));
    return d;
}
__device__ __forceinline__ float2 unpk(u64 v) {
    unsigned lo, hi;
    asm("mov.b64 {%0, %1}, %2;" : "=r"(lo), "=r"(hi) : "l"(v));
    return make_float2(__uint_as_float(lo), __uint_as_float(hi));
}

__device__ __forceinline__ void push_all(const void* lptr, float4 v) {
    uint32_t la = sm2u(lptr);
#pragma unroll
    for (int pr = 0; pr < CSZ; pr++) {
        uint32_t ra;
        asm("mapa.shared::cluster.u32 %0, %1, %2;" : "=r"(ra) : "r"(la), "r"(pr));
        asm volatile("st.shared::cluster.v4.f32 [%0], {%1, %2, %3, %4};"
                     :: "r"(ra), "f"(v.x), "f"(v.y), "f"(v.z), "f"(v.w)
                     : "memory");
    }
}

// Fast transcendentals (rel err ~1e-6, budget 1e-3).
__device__ __forceinline__ float sigf(float x) {
    return __fdividef(1.0f, 1.0f + __expf(-x));
}
__device__ __forceinline__ float tanhf_(float x) {
    return 1.0f - __fdividef(2.0f, __expf(2.0f * x) + 1.0f);
}

// Output-stationary sliced GEMV (unchanged semantics from R13).
template <int CG, int KP, int KLEN, int WS>
__device__ __forceinline__ void gemv4(const float* __restrict__ W,
                                      const float4* __restrict__ act,
                                      float4* __restrict__ part, int tid) {
    const int cg = tid & (CG - 1);
    const int kp = tid / CG;
    const float* wp = W + (size_t)(kp * KLEN) * WS + (cg << 2);
    const ulonglong2* ap = reinterpret_cast<const ulonglong2*>(act + kp * KLEN);
    u64 a01[4] = {0ull, 0ull, 0ull, 0ull};
    u64 a23[4] = {0ull, 0ull, 0ull, 0ull};
#pragma unroll 8
    for (int k = 0; k < KLEN; k++) {
        float4 w = *reinterpret_cast<const float4*>(wp + (size_t)k * WS);
        ulonglong2 av = ap[k];
        u64 w0 = rep2(w.x), w1 = rep2(w.y), w2 = rep2(w.z), w3 = rep2(w.w);
        a01[0] = fma2(w0, av.x, a01[0]);  a23[0] = fma2(w0, av.y, a23[0]);
        a01[1] = fma2(w1, av.x, a01[1]);  a23[1] = fma2(w1, av.y, a23[1]);
        a01[2] = fma2(w2, av.x, a01[2]);  a23[2] = fma2(w2, av.y, a23[2]);
        a01[3] = fma2(w3, av.x, a01[3]);  a23[3] = fma2(w3, av.y, a23[3]);
    }
#pragma unroll
    for (int cc = 0; cc < 4; cc++) {
        float2 lo = unpk(a01[cc]);
        float2 hi = unpk(a23[cc]);
        part[kp * (CG * 4) + (cg << 2) + cc] = make_float4(lo.x, lo.y, hi.x, hi.y);
    }
}

template <int NC, int KP>
__device__ __forceinline__ float4 combine(const float4* __restrict__ part, int j) {
    float4 s = part[j];
#pragma unroll
    for (int kp = 1; kp < KP; kp++) {
        float4 q = part[kp * NC + j];
        s.x += q.x; s.y += q.y; s.z += q.z; s.w += q.w;
    }
    return s;
}

// rp-partitioned reduce: warps 0..7 (tid<256) hold rows {0,1}; warps 8..15 rows
// {2,3}. v[i] becomes the sum over this thread's OWN rp group. bc[0..NV) holds
// group-0 sums, bc[NV..2NV) group-1 sums (persist until next reduce).
template <int NV>
__device__ __forceinline__ void red_rp(float* v, Smem* s, int tid, int lane, int warp) {
#pragma unroll
    for (int i = 0; i < NV; i++) {
        float x = v[i];
#pragma unroll
        for (int o = 16; o > 0; o >>= 1) x += __shfl_xor_sync(0xffffffffu, x, o);
        if (lane == 0) s->red[warp][i] = x;
    }
    __syncthreads();
    if (tid == 0) {
#pragma unroll
        for (int i = 0; i < NV; i++) {
            float a = 0.f, b = 0.f;
#pragma unroll
            for (int w = 0; w < 8; w++) { a += s->red[w][i]; b += s->red[w + 8][i]; }
            s->bc[i] = a; s->bc[NV + i] = b;
        }
    }
    __syncthreads();
    const int off = (tid >= 256) ? NV : 0;
#pragma unroll
    for (int i = 0; i < NV; i++) v[i] = s->bc[off + i];
}

// Plain block-wide reduce (all 16 warps), broadcast to all threads.
template <int NV>
__device__ __forceinline__ void blk_reduce(float* v, Smem* s, int tid, int lane, int warp) {
#pragma unroll
    for (int i = 0; i < NV; i++) {
        float x = v[i];
#pragma unroll
        for (int o = 16; o > 0; o >>= 1) x += __shfl_xor_sync(0xffffffffu, x, o);
        if (lane == 0) s->red[warp][i] = x;
    }
    __syncthreads();
    if (tid == 0) {
#pragma unroll
        for (int i = 0; i < NV; i++) {
            float acc = s->red[0][i];
#pragma unroll
            for (int w = 1; w < NWARP; w++) acc += s->red[w][i];
            s->bc[i] = acc;
        }
    }
    __syncthreads();
#pragma unroll
    for (int i = 0; i < NV; i++) v[i] = s->bc[i];
}

__global__ void __launch_bounds__(NT) __cluster_dims__(CSZ, 1, 1)
xlstm_kernel(Ptrs p) {
    extern __shared__ char smem_raw[];
    Smem* s = reinterpret_cast<Smem*>(smem_raw);

    const int tid  = threadIdx.x;
    const int lane = tid & 31;
    const int warp = tid >> 5;
    const int col  = tid & 255;     // elementwise column
    const int rp   = tid >> 8;      // row-pair: 0 -> rows{0,1}, 1 -> rows{2,3}
    const uint32_t rk = ctarank();
    const int row0 = (blockIdx.x & ~(CSZ - 1));
    const float invH  = 1.0f / (float)HID;
    const float invH2 = 1.0f / (float)H2;

    if (tid < HID) {
        const float4 z4 = make_float4(0.f, 0.f, 0.f, 0.f);
#pragma unroll
        for (int l = 0; l < LNUM; l++) { s->h[l][tid] = z4; s->c[l][tid] = z4; }
    }
    __syncthreads();

    for (int t = 0; t < TT; t++) {
        // ---- xt = [disp_t | params], row-minor ----
        if (tid < TF * 4) {
            int j = tid >> 2, rr = tid & 3;
            float v = (j == 0) ? p.disp[(size_t)(row0 + rr) * TT + t]
                               : p.params[(size_t)(row0 + rr) * NF + (j - 1)];
            reinterpret_cast<float*>(&s->xt[j])[rr] = v;
        }
        __syncthreads();

        // ---- embed + skip, (col, rp) parallel ----
        {
            float eb = p.embed_b[col];
            float2 e = make_float2(eb, eb);
#pragma unroll
            for (int k = 0; k < TF; k++) {
                float w = p.embed_w[k * HID + col];
                float2 xt2 = reinterpret_cast<const float2*>(&s->xt[k])[rp];
                e.x += xt2.x * w; e.y += xt2.y * w;
            }
            if (col < H2) {
                float sb = p.skip_b[col];
                float2 sk = make_float2(sb, sb);
#pragma unroll
                for (int k = 0; k < TF; k++) {
                    float w = p.skip_w[k * H2 + col];
                    float2 xt2 = reinterpret_cast<const float2*>(&s->xt[k])[rp];
                    sk.x += xt2.x * w; sk.y += xt2.y * w;
                }
                sk.x = fmaxf(sk.x, 0.f); sk.y = fmaxf(sk.y, 0.f);
                reinterpret_cast<float2*>(&s->skip[col])[rp] = sk;
            }
            float r4[4] = { e.x, e.x * e.x, e.y, e.y * e.y };
            red_rp<4>(r4, s, tid, lane, warp);
            float g = p.embed_g[col], b = p.embed_beta[col];
            float2 xo;
            float mu, var, rs;
            mu = r4[0] * invH; var = r4[1] * invH - mu * mu; rs = rsqrtf(var + LN_EPS);
            xo.x = fmaxf((e.x - mu) * rs * g + b, 0.f);
            mu = r4[2] * invH; var = r4[3] * invH - mu * mu; rs = rsqrtf(var + LN_EPS);
            xo.y = fmaxf((e.y - mu) * rs * g + b, 0.f);
            reinterpret_cast<float2*>(&s->x[col])[rp] = xo;
        }
        __syncthreads();

        // ---- layers ----
#pragma unroll 1
        for (int l = 0; l < LNUM; l++) {
            float2 resid;
            // LN(x), LN(h) -> gin = [xn | hn]
            {
                float2 xv = reinterpret_cast<const float2*>(&s->x[col])[rp];
                float2 hv = reinterpret_cast<const float2*>(&s->h[l][col])[rp];
                resid = xv;
                float r8[8] = { xv.x, xv.x * xv.x, xv.y, xv.y * xv.y,
                                hv.x, hv.x * hv.x, hv.y, hv.y * hv.y };
                red_rp<8>(r8, s, tid, lane, warp);
                float ig = p.inln_g[l * HID + col], ib = p.inln_b[l * HID + col];
                float hg = p.hln_g[l * HID + col],  hb = p.hln_b[l * HID + col];
                float2 xn, hn;
                float mu, var, rs;
                mu = r8[0] * invH; var = r8[1] * invH - mu * mu; rs = rsqrtf(var + LN_EPS);
                xn.x = (xv.x - mu) * rs * ig + ib;
                mu = r8[2] * invH; var = r8[3] * invH - mu * mu; rs = rsqrtf(var + LN_EPS);
                xn.y = (xv.y - mu) * rs * ig + ib;
                mu = r8[4] * invH; var = r8[5] * invH - mu * mu; rs = rsqrtf(var + LN_EPS);
                hn.x = (hv.x - mu) * rs * hg + hb;
                mu = r8[6] * invH; var = r8[7] * invH - mu * mu; rs = rsqrtf(var + LN_EPS);
                hn.y = (hv.y - mu) * rs * hg + hb;
                reinterpret_cast<float2*>(&s->gin[col])[rp]       = xn;
                reinterpret_cast<float2*>(&s->gin[HID + col])[rp] = hn;
            }
            __syncthreads();

            // gates GEMV slice: cols [rk*256,+256) of 1024, k=512
            gemv4<64, 8, 64, 4 * HID>(
                p.gates_w + (size_t)l * (2 * HID) * (4 * HID) + rk * 256,
                s->gin, s->part, tid);
            __syncthreads();
            if (tid < 256) {
                float4 g = combine<256, 8>(s->part, tid);
                float bb = p.gates_b[l * 4 * HID + rk * 256 + tid];
                g.x += bb; g.y += bb; g.z += bb; g.w += bb;
                push_all(&s->g4[rk * 256 + tid], g);
            }
            __syncthreads();   // part reuse

            // attention GEMV slice (old c): cols [rk*64,+64) of 256
            gemv4<16, 32, 8, HID>(
                p.aw1 + (size_t)l * HID * HID + rk * 64,
                s->c[l], s->part, tid);
            __syncthreads();
            {
                float r4[4] = {0.f, 0.f, 0.f, 0.f};
                if (tid < 64) {
                    float4 a = combine<64, 32>(s->part, tid);
                    float ab = p.ab1[l * HID + rk * 64 + tid];
                    float w2 = p.aw2[l * HID + rk * 64 + tid];
                    r4[0] = tanhf_(a.x + ab) * w2;
                    r4[1] = tanhf_(a.y + ab) * w2;
                    r4[2] = tanhf_(a.z + ab) * w2;
                    r4[3] = tanhf_(a.w + ab) * w2;
                }
                blk_reduce<4>(r4, s, tid, lane, warp);
                if (tid == 0)
                    push_all(&s->attnp[rk], make_float4(r4[0], r4[1], r4[2], r4[3]));
            }
            CLUSTER_SYNC();   // g4 + attnp assembled everywhere

            // c/h update, (col, rp) parallel
            {
                float4 pa = s->attnp[0], pb = s->attnp[1],
                       pc = s->attnp[2], pd = s->attnp[3];
                float4 sum4 = make_float4(pa.x + pb.x + pc.x + pd.x,
                                          pa.y + pb.y + pc.y + pd.y,
                                          pa.z + pb.z + pc.z + pd.z,
                                          pa.w + pb.w + pc.w + pd.w);
                float2 ss = reinterpret_cast<const float2*>(&sum4)[rp];
                float ab2v = p.ab2[l];
                float2 imp = make_float2(sigf(ss.x + ab2v), sigf(ss.y + ab2v));
                float2 gi = reinterpret_cast<const float2*>(&s->g4[col])[rp];
                float2 gf = reinterpret_cast<const float2*>(&s->g4[HID + col])[rp];
                float2 gg = reinterpret_cast<const float2*>(&s->g4[2 * HID + col])[rp];
                float2 go = reinterpret_cast<const float2*>(&s->g4[3 * HID + col])[rp];
                float2 co = reinterpret_cast<const float2*>(&s->c[l][col])[rp];
                float2 cp;
                cp.x = (sigf(gf.x) * co.x + sigf(gi.x) * tanhf_(gg.x)) * imp.x;
                cp.y = (sigf(gf.y) * co.y + sigf(gi.y) * tanhf_(gg.y)) * imp.y;
                float r4[4] = { cp.x, cp.x * cp.x, cp.y, cp.y * cp.y };
                red_rp<4>(r4, s, tid, lane, warp);
                float sg = p.sln_g[l * HID + col], sb = p.sln_b[l * HID + col];
                float2 cn, hv;
                float mu, var, rs;
                mu = r4[0] * invH; var = r4[1] * invH - mu * mu; rs = rsqrtf(var + LN_EPS);
                cn.x = (cp.x - mu) * rs * sg + sb;  hv.x = sigf(go.x) * tanhf_(cn.x);
                mu = r4[2] * invH; var = r4[3] * invH - mu * mu; rs = rsqrtf(var + LN_EPS);
                cn.y = (cp.y - mu) * rs * sg + sb;  hv.y = sigf(go.y) * tanhf_(cn.y);
                reinterpret_cast<float2*>(&s->c[l][col])[rp] = cn;
                reinterpret_cast<float2*>(&s->h[l][col])[rp] = hv;
                reinterpret_cast<float2*>(&s->x[col])[rp]    = hv;
            }
            __syncthreads();

            // residual GEMV1 slice: cols [rk*128,+128) of 512, k=256
            gemv4<32, 16, 16, 2 * HID>(
                p.rw1 + (size_t)l * HID * (2 * HID) + rk * 128,
                s->x, s->part, tid);
            __syncthreads();
            if (tid < 128) {
                float4 v = combine<128, 16>(s->part, tid);
                float bb = p.rb1[l * 2 * HID + rk * 128 + tid];
                v.x = fmaxf(v.x + bb, 0.f); v.y = fmaxf(v.y + bb, 0.f);
                v.z = fmaxf(v.z + bb, 0.f); v.w = fmaxf(v.w + bb, 0.f);
                push_all(&s->t1[rk * 128 + tid], v);
            }
            CLUSTER_SYNC();   // t1 assembled

            // residual GEMV2 slice: cols [rk*64,+64) of 256, k=512
            gemv4<16, 32, 16, HID>(
                p.rw2 + (size_t)l * (2 * HID) * HID + rk * 64,
                s->t1, s->part, tid);
            __syncthreads();
            if (tid < 64) {
                float4 v = combine<64, 32>(s->part, tid);
                int gcol = rk * 64 + tid;
                float bb = p.rb2[l * HID + gcol];
                float4 xv = s->x[gcol];
                v.x += bb + xv.x; v.y += bb + xv.y;
                v.z += bb + xv.z; v.w += bb + xv.w;
                push_all(&s->gin[gcol], v);
            }
            CLUSTER_SYNC();   // pre-LN vector assembled

            // r-LN + residual, (col, rp) parallel
            {
                float2 v = reinterpret_cast<const float2*>(&s->gin[col])[rp];
                float r4[4] = { v.x, v.x * v.x, v.y, v.y * v.y };
                red_rp<4>(r4, s, tid, lane, warp);
                float rg = p.rln_g[l * HID + col], rb = p.rln_b[l * HID + col];
                float2 xo;
                float mu, var, rs;
                mu = r4[0] * invH; var = r4[1] * invH - mu * mu; rs = rsqrtf(var + LN_EPS);
                xo.x = (v.x - mu) * rs * rg + rb + resid.x;
                mu = r4[2] * invH; var = r4[3] * invH - mu * mu; rs = rsqrtf(var + LN_EPS);
                xo.y = (v.y - mu) * rs * rg + rb + resid.y;
                reinterpret_cast<float2*>(&s->x[col])[rp] = xo;
            }
            __syncthreads();
        }

        // ---- output head ----
        gemv4<8, 64, 6, H2>(p.ow1 + rk * 32, s->x, s->part, tid);
        __syncthreads();
        if (tid < 32) {
            float4 v = combine<32, 64>(s->part, tid);
            float bb = p.ob1[rk * 32 + tid];
            v.x += bb; v.y += bb; v.z += bb; v.w += bb;
            push_all(&s->hd[rk * 32 + tid], v);
        }
        CLUSTER_SYNC();   // hd assembled
        {
            const bool act = (col < H2);
            float2 zv = make_float2(0.f, 0.f);
            if (act) zv = reinterpret_cast<const float2*>(&s->hd[col])[rp];
            float r4[4] = { zv.x, zv.x * zv.x, zv.y, zv.y * zv.y };
            if (!act) { r4[0] = r4[1] = r4[2] = r4[3] = 0.f; }
            red_rp<4>(r4, s, tid, lane, warp);
            float r2[2] = { 0.f, 0.f };
            if (act) {
                float og = p.oln_g[col], ob = p.oln_b[col];
                float w2 = p.ow2[col];
                float mu, var, rs;
                mu = r4[0] * invH2; var = r4[1] * invH2 - mu * mu; rs = rsqrtf(var + LN_EPS);
                r2[0] = fmaxf((zv.x - mu) * rs * og + ob, 0.f) * w2;
                mu = r4[2] * invH2; var = r4[3] * invH2 - mu * mu; rs = rsqrtf(var + LN_EPS);
                r2[1] = fmaxf((zv.y - mu) * rs * og + ob, 0.f) * w2;
            }
            red_rp<2>(r2, s, tid, lane, warp);
            // bc[0..3] = rows 0..3 (persists until next reduce's bc write)
            if (tid < 4)
                p.out[(size_t)(row0 + tid) * TT + t] = s->bc[tid] + p.ob2[0];
        }
        __syncthreads();
    }
}

extern "C" void kernel_launch(void* const* d_in, const int* in_sizes, int n_in,
                              void* d_out, int out_size) {
    Ptrs p;
    p.params     = (const float*)d_in[0];
    p.disp       = (const float*)d_in[1];
    p.embed_w    = (const float*)d_in[2];
    p.embed_b    = (const float*)d_in[3];
    p.embed_g    = (const float*)d_in[4];
    p.embed_beta = (const float*)d_in[5];
    p.skip_w     = (const float*)d_in[6];
    p.skip_b     = (const float*)d_in[7];
    p.gates_w    = (const float*)d_in[8];
    p.gates_b    = (const float*)d_in[9];
    p.inln_g     = (const float*)d_in[10];
    p.inln_b     = (const float*)d_in[11];
    p.hln_g      = (const float*)d_in[12];
    p.hln_b      = (const float*)d_in[13];
    p.sln_g      = (const float*)d_in[14];
    p.sln_b      = (const float*)d_in[15];
    p.aw1        = (const float*)d_in[16];
    p.ab1        = (const float*)d_in[17];
    p.aw2        = (const float*)d_in[18];
    p.ab2        = (const float*)d_in[19];
    p.rw1        = (const float*)d_in[20];
    p.rb1        = (const float*)d_in[21];
    p.rw2        = (const float*)d_in[22];
    p.rb2        = (const float*)d_in[23];
    p.rln_g      = (const float*)d_in[24];
    p.rln_b      = (const float*)d_in[25];
    p.ow1        = (const float*)d_in[26];
    p.ob1        = (const float*)d_in[27];
    p.oln_g      = (const float*)d_in[28];
    p.oln_b      = (const float*)d_in[29];
    p.ow2        = (const float*)d_in[30];
    p.ob2        = (const float*)d_in[31];
    p.out        = (float*)d_out;

    cudaFuncSetAttribute(xlstm_kernel,
                         cudaFuncAttributeMaxDynamicSharedMemorySize,
                         (int)sizeof(Smem));
    xlstm_kernel<<<BB, NT, sizeof(Smem)>>>(p);
}

// round 17
// speedup vs baseline: 4.1565x; 1.5591x over previous
#include <cuda_runtime.h>
#include <cstdint>

// ---------------------------------------------------------------------------
// xLSTM_Model2 — cluster-sliced persistent kernel, v3 (re-bench; R16 run died
// to a container-level infra failure before executing).
// 32 clusters x 4 CTAs x 512 threads. Cluster owns 4 batch rows for the whole
// T=256 recurrence. CTA rank r computes the r-th quarter of every GEMV's
// output columns (weights reused across 4 rows via packed fma.rn.f32x2),
// broadcasts slices via DSMEM + barrier.cluster.
// v3: all small params/biases/inputs cached in SMEM at t=0 (steady loop has
// zero global loads except the 5 big weight streams); single-barrier parallel
// reductions (no tid0 serial chain); conflict-free part-buffer indexing.
// ---------------------------------------------------------------------------

#define LNUM   3
#define HID    256
#define H2     128
#define NF     16
#define TF     17
#define BB     128
#define TT     256
#define LN_EPS 1e-5f
#define NT     512
#define NWARP  16
#define CSZ    4

typedef unsigned long long u64;

struct Ptrs {
    const float* __restrict__ params;
    const float* __restrict__ disp;
    const float* __restrict__ embed_w;
    const float* __restrict__ embed_b;
    const float* __restrict__ embed_g;
    const float* __restrict__ embed_beta;
    const float* __restrict__ skip_w;
    const float* __restrict__ skip_b;
    const float* __restrict__ gates_w;
    const float* __restrict__ gates_b;
    const float* __restrict__ inln_g;
    const float* __restrict__ inln_b;
    const float* __restrict__ hln_g;
    const float* __restrict__ hln_b;
    const float* __restrict__ sln_g;
    const float* __restrict__ sln_b;
    const float* __restrict__ aw1;
    const float* __restrict__ ab1;
    const float* __restrict__ aw2;
    const float* __restrict__ ab2;
    const float* __restrict__ rw1;
    const float* __restrict__ rb1;
    const float* __restrict__ rw2;
    const float* __restrict__ rb2;
    const float* __restrict__ rln_g;
    const float* __restrict__ rln_b;
    const float* __restrict__ ow1;
    const float* __restrict__ ob1;
    const float* __restrict__ oln_g;
    const float* __restrict__ oln_b;
    const float* __restrict__ ow2;
    const float* __restrict__ ob2;
    float* __restrict__ out;
};

// Row-minor activations: buf[dim] = float4 of rows 0..3.
struct __align__(16) Smem {
    float4 x[HID];
    float4 skip[H2];        // MUST follow x: head GEMV reads [x | skip] as 384
    float4 h[LNUM][HID];
    float4 c[LNUM][HID];
    float4 gin[2 * HID];    // [xn | hn]; reused as r2 pre-LN buffer
    float4 g4[4 * HID];
    float4 t1[2 * HID];
    float4 hd[H2];
    float4 attnp[CSZ];
    float4 part[2304];      // padded (kp, cc, cg) layout, max = head 64*4*9
    float  red[16][16];     // transposed: red[value][warp]
    // ---- parameter / input caches (filled once at t=0) ----
    float disp_c[4][TT];
    float par_c[NF][4];     // row-minor params_input
    float embw[TF * HID];
    float skw[TF * H2];
    float embb[HID], embg[HID], embbt[HID], skb[H2];
    float lnp[LNUM][8][HID];   // 0:inln_g 1:inln_b 2:hln_g 3:hln_b 4:sln_g 5:sln_b 6:rln_g 7:rln_b
    float gbias[LNUM][4 * HID];
    float rb1c[LNUM][2 * HID];
    float rb2c[LNUM][HID];
    float ab1c[LNUM][HID];
    float aw2c[LNUM][HID];
    float ab2c[LNUM];
    float ob1c[H2], olng[H2], olnb[H2], ow2c[H2];
    float ob2c;
};

__device__ __forceinline__ uint32_t sm2u(const void* p) {
    uint32_t a;
    asm("{ .reg .u64 t; cvta.to.shared.u64 t, %1; cvt.u32.u64 %0, t; }"
        : "=r"(a) : "l"(p));
    return a;
}
__device__ __forceinline__ uint32_t ctarank() {
    uint32_t r; asm("mov.u32 %0, %%cluster_ctarank;" : "=r"(r)); return r;
}
#define CLUSTER_SYNC() do { \
    asm volatile("barrier.cluster.arrive.aligned;" ::: "memory"); \
    asm volatile("barrier.cluster.wait.aligned;"   ::: "memory"); \
} while (0)

__device__ __forceinline__ u64 fma2(u64 a, u64 b, u64 c) {
    u64 d;
    asm("fma.rn.f32x2 %0, %1, %2, %3;" : "=l"(d) : "l"(a), "l"(b), "l"(c));
    return d;
}
__device__ __forceinline__ u64 rep2(float x) {
    u64 d; unsigned xb = __float_as_uint(x);
    asm("mov.b64 %0, {%1, %1};" : "=l"(d) : "r"(xb));
    return d;
}
__device__ __forceinline__ float2 unpk(u64 v) {
    unsigned lo, hi;
    asm("mov.b64 {%0, %1}, %2;" : "=r"(lo), "=r"(hi) : "l"(v));
    return make_float2(__uint_as_float(lo), __uint_as_float(hi));
}

__device__ __forceinline__ void push_all(const void* lptr, float4 v) {
    uint32_t la = sm2u(lptr);
#pragma unroll
    for (int pr = 0; pr < CSZ; pr++) {
        uint32_t ra;
        asm("mapa.shared::cluster.u32 %0, %1, %2;" : "=r"(ra) : "r"(la), "r"(pr));
        asm volatile("st.shared::cluster.v4.f32 [%0], {%1, %2, %3, %4};"
                     :: "r"(ra), "f"(v.x), "f"(v.y), "f"(v.z), "f"(v.w)
                     : "memory");
    }
}

__device__ __forceinline__ float sigf(float x) {
    return __fdividef(1.0f, 1.0f + __expf(-x));
}
__device__ __forceinline__ float tanhf_(float x) {
    return 1.0f - __fdividef(2.0f, __expf(2.0f * x) + 1.0f);
}

// Output-stationary sliced GEMV. part layout: [kp][cc][cg] with cc-stride
// CG+1 (padding kills the 16-way bank conflicts of the R15 layout: lanes
// store consecutive float4s).
template <int CG, int KP, int KLEN, int WS>
__device__ __forceinline__ void gemv4(const float* __restrict__ W,
                                      const float4* __restrict__ act,
                                      float4* __restrict__ part, int tid) {
    const int cg = tid & (CG - 1);
    const int kp = tid / CG;
    const float* wp = W + (size_t)(kp * KLEN) * WS + (cg << 2);
    const ulonglong2* ap = reinterpret_cast<const ulonglong2*>(act + kp * KLEN);
    u64 a01[4] = {0ull, 0ull, 0ull, 0ull};
    u64 a23[4] = {0ull, 0ull, 0ull, 0ull};
#pragma unroll 8
    for (int k = 0; k < KLEN; k++) {
        float4 w = *reinterpret_cast<const float4*>(wp + (size_t)k * WS);
        ulonglong2 av = ap[k];
        u64 w0 = rep2(w.x), w1 = rep2(w.y), w2 = rep2(w.z), w3 = rep2(w.w);
        a01[0] = fma2(w0, av.x, a01[0]);  a23[0] = fma2(w0, av.y, a23[0]);
        a01[1] = fma2(w1, av.x, a01[1]);  a23[1] = fma2(w1, av.y, a23[1]);
        a01[2] = fma2(w2, av.x, a01[2]);  a23[2] = fma2(w2, av.y, a23[2]);
        a01[3] = fma2(w3, av.x, a01[3]);  a23[3] = fma2(w3, av.y, a23[3]);
    }
    float4* pb = part + kp * 4 * (CG + 1) + cg;
#pragma unroll
    for (int cc = 0; cc < 4; cc++) {
        float2 lo = unpk(a01[cc]);
        float2 hi = unpk(a23[cc]);
        pb[cc * (CG + 1)] = make_float4(lo.x, lo.y, hi.x, hi.y);
    }
}

// Combine for output col j (within slice): produced by cg=j>>2, cc=j&3.
template <int CG, int KP>
__device__ __forceinline__ float4 combine(const float4* __restrict__ part, int j) {
    const int idx0 = (j & 3) * (CG + 1) + (j >> 2);
    float4 s = part[idx0];
#pragma unroll
    for (int kp = 1; kp < KP; kp++) {
        float4 q = part[kp * 4 * (CG + 1) + idx0];
        s.x += q.x; s.y += q.y; s.z += q.z; s.w += q.w;
    }
    return s;
}

// Single-barrier reduction. SPLIT=2: two groups of 8 warps (tid<256 = rows
// {0,1}, tid>=256 = rows {2,3}), each thread gets its OWN group's sums.
// SPLIT=1: block-wide sum for everyone. No tid0 serial chain: every thread
// sums the warp partials itself via LDS.128 (broadcast, conflict-free).
template <int NV, int SPLIT>
__device__ __forceinline__ void redx(float* v, Smem* s, int tid, int lane, int warp) {
#pragma unroll
    for (int i = 0; i < NV; i++) {
        float x = v[i];
#pragma unroll
        for (int o = 16; o > 0; o >>= 1) x += __shfl_xor_sync(0xffffffffu, x, o);
        if (lane == 0) s->red[i][warp] = x;
    }
    __syncthreads();
    const int base = (SPLIT == 2 && tid >= 256) ? 8 : 0;
#pragma unroll
    for (int i = 0; i < NV; i++) {
        float4 A = *reinterpret_cast<const float4*>(&s->red[i][base]);
        float4 B = *reinterpret_cast<const float4*>(&s->red[i][base + 4]);
        float sum = ((A.x + A.y) + (A.z + A.w)) + ((B.x + B.y) + (B.z + B.w));
        if (SPLIT == 1) {
            float4 C = *reinterpret_cast<const float4*>(&s->red[i][8]);
            float4 D = *reinterpret_cast<const float4*>(&s->red[i][12]);
            sum += ((C.x + C.y) + (C.z + C.w)) + ((D.x + D.y) + (D.z + D.w));
        }
        v[i] = sum;
    }
}

__global__ void __launch_bounds__(NT) __cluster_dims__(CSZ, 1, 1)
xlstm_kernel(Ptrs p) {
    extern __shared__ char smem_raw[];
    Smem* s = reinterpret_cast<Smem*>(smem_raw);

    const int tid  = threadIdx.x;
    const int lane = tid & 31;
    const int warp = tid >> 5;
    const int col  = tid & 255;     // elementwise column
    const int rp   = tid >> 8;      // row-pair: 0 -> rows{0,1}, 1 -> rows{2,3}
    const uint32_t rk = ctarank();
    const int row0 = (blockIdx.x & ~(CSZ - 1));
    const float invH  = 1.0f / (float)HID;
    const float invH2 = 1.0f / (float)H2;

    // ================= one-time cache fill =================
    for (int i = tid; i < TF * HID; i += NT) s->embw[i] = p.embed_w[i];
    for (int i = tid; i < TF * H2;  i += NT) s->skw[i]  = p.skip_w[i];
    for (int i = tid; i < LNUM * 4 * HID; i += NT) (&s->gbias[0][0])[i] = p.gates_b[i];
    for (int i = tid; i < LNUM * 2 * HID; i += NT) (&s->rb1c[0][0])[i]  = p.rb1[i];
    if (tid < HID) {
        s->embb[tid]  = p.embed_b[tid];
        s->embg[tid]  = p.embed_g[tid];
        s->embbt[tid] = p.embed_beta[tid];
#pragma unroll
        for (int l = 0; l < LNUM; l++) {
            s->lnp[l][0][tid] = p.inln_g[l * HID + tid];
            s->lnp[l][1][tid] = p.inln_b[l * HID + tid];
            s->lnp[l][2][tid] = p.hln_g[l * HID + tid];
            s->lnp[l][3][tid] = p.hln_b[l * HID + tid];
            s->lnp[l][4][tid] = p.sln_g[l * HID + tid];
            s->lnp[l][5][tid] = p.sln_b[l * HID + tid];
            s->lnp[l][6][tid] = p.rln_g[l * HID + tid];
            s->lnp[l][7][tid] = p.rln_b[l * HID + tid];
            s->rb2c[l][tid]   = p.rb2[l * HID + tid];
            s->ab1c[l][tid]   = p.ab1[l * HID + tid];
            s->aw2c[l][tid]   = p.aw2[l * HID + tid];
        }
        const float4 z4 = make_float4(0.f, 0.f, 0.f, 0.f);
#pragma unroll
        for (int l = 0; l < LNUM; l++) { s->h[l][tid] = z4; s->c[l][tid] = z4; }
    }
    if (tid < H2) {
        s->ob1c[tid] = p.ob1[tid];
        s->olng[tid] = p.oln_g[tid];
        s->olnb[tid] = p.oln_b[tid];
        s->ow2c[tid] = p.ow2[tid];
        s->skb[tid]  = p.skip_b[tid];
    }
    if (tid < LNUM) s->ab2c[tid] = p.ab2[tid];
    if (tid == 0)   s->ob2c = p.ob2[0];
    for (int i = tid; i < 4 * TT; i += NT) {
        int rr = i >> 8, tt = i & 255;
        s->disp_c[rr][tt] = p.disp[(size_t)(row0 + rr) * TT + tt];
    }
    if (tid < NF * 4) {
        int k = tid >> 2, rr = tid & 3;
        s->par_c[k][rr] = p.params[(size_t)(row0 + rr) * NF + k];
    }
    __syncthreads();

    // ================= recurrence =================
    for (int t = 0; t < TT; t++) {
        // ---- embed + skip: pure-SMEM, no staging phase ----
        {
            float eb = s->embb[col];
            float2 e = make_float2(eb, eb);
            float2 d = make_float2(s->disp_c[rp * 2][t], s->disp_c[rp * 2 + 1][t]);
            float w0 = s->embw[col];
            e.x += d.x * w0; e.y += d.y * w0;
#pragma unroll
            for (int k = 1; k < TF; k++) {
                float w = s->embw[k * HID + col];
                float2 pv = *reinterpret_cast<const float2*>(&s->par_c[k - 1][rp * 2]);
                e.x += pv.x * w; e.y += pv.y * w;
            }
            if (col < H2) {
                float sb = s->skb[col];
                float2 sk = make_float2(sb, sb);
                float ws0 = s->skw[col];
                sk.x += d.x * ws0; sk.y += d.y * ws0;
#pragma unroll
                for (int k = 1; k < TF; k++) {
                    float w = s->skw[k * H2 + col];
                    float2 pv = *reinterpret_cast<const float2*>(&s->par_c[k - 1][rp * 2]);
                    sk.x += pv.x * w; sk.y += pv.y * w;
                }
                reinterpret_cast<float2*>(&s->skip[col])[rp] =
                    make_float2(fmaxf(sk.x, 0.f), fmaxf(sk.y, 0.f));
            }
            float r4[4] = { e.x, e.x * e.x, e.y, e.y * e.y };
            redx<4, 2>(r4, s, tid, lane, warp);
            float g = s->embg[col], b = s->embbt[col];
            float2 xo;
            float mu, var, rs;
            mu = r4[0] * invH; var = r4[1] * invH - mu * mu; rs = rsqrtf(var + LN_EPS);
            xo.x = fmaxf((e.x - mu) * rs * g + b, 0.f);
            mu = r4[2] * invH; var = r4[3] * invH - mu * mu; rs = rsqrtf(var + LN_EPS);
            xo.y = fmaxf((e.y - mu) * rs * g + b, 0.f);
            reinterpret_cast<float2*>(&s->x[col])[rp] = xo;
        }
        __syncthreads();

        // ---- layers ----
#pragma unroll 1
        for (int l = 0; l < LNUM; l++) {
            float2 resid;
            // LN(x), LN(h) -> gin = [xn | hn]
            {
                float2 xv = reinterpret_cast<const float2*>(&s->x[col])[rp];
                float2 hv = reinterpret_cast<const float2*>(&s->h[l][col])[rp];
                resid = xv;
                float r8[8] = { xv.x, xv.x * xv.x, xv.y, xv.y * xv.y,
                                hv.x, hv.x * hv.x, hv.y, hv.y * hv.y };
                redx<8, 2>(r8, s, tid, lane, warp);
                float ig = s->lnp[l][0][col], ib = s->lnp[l][1][col];
                float hg = s->lnp[l][2][col], hb = s->lnp[l][3][col];
                float2 xn, hn;
                float mu, var, rs;
                mu = r8[0] * invH; var = r8[1] * invH - mu * mu; rs = rsqrtf(var + LN_EPS);
                xn.x = (xv.x - mu) * rs * ig + ib;
                mu = r8[2] * invH; var = r8[3] * invH - mu * mu; rs = rsqrtf(var + LN_EPS);
                xn.y = (xv.y - mu) * rs * ig + ib;
                mu = r8[4] * invH; var = r8[5] * invH - mu * mu; rs = rsqrtf(var + LN_EPS);
                hn.x = (hv.x - mu) * rs * hg + hb;
                mu = r8[6] * invH; var = r8[7] * invH - mu * mu; rs = rsqrtf(var + LN_EPS);
                hn.y = (hv.y - mu) * rs * hg + hb;
                reinterpret_cast<float2*>(&s->gin[col])[rp]       = xn;
                reinterpret_cast<float2*>(&s->gin[HID + col])[rp] = hn;
            }
            __syncthreads();

            // gates GEMV slice: cols [rk*256,+256) of 1024, k=512
            gemv4<64, 8, 64, 4 * HID>(
                p.gates_w + (size_t)l * (2 * HID) * (4 * HID) + rk * 256,
                s->gin, s->part, tid);
            __syncthreads();
            if (tid < 256) {
                float4 g = combine<64, 8>(s->part, tid);
                float bb = s->gbias[l][rk * 256 + tid];
                g.x += bb; g.y += bb; g.z += bb; g.w += bb;
                push_all(&s->g4[rk * 256 + tid], g);
            }
            __syncthreads();   // part reuse

            // attention GEMV slice (old c): cols [rk*64,+64) of 256
            gemv4<16, 32, 8, HID>(
                p.aw1 + (size_t)l * HID * HID + rk * 64,
                s->c[l], s->part, tid);
            __syncthreads();
            {
                float r4[4] = {0.f, 0.f, 0.f, 0.f};
                if (tid < 64) {
                    float4 a = combine<16, 32>(s->part, tid);
                    float ab = s->ab1c[l][rk * 64 + tid];
                    float w2 = s->aw2c[l][rk * 64 + tid];
                    r4[0] = tanhf_(a.x + ab) * w2;
                    r4[1] = tanhf_(a.y + ab) * w2;
                    r4[2] = tanhf_(a.z + ab) * w2;
                    r4[3] = tanhf_(a.w + ab) * w2;
                }
                redx<4, 1>(r4, s, tid, lane, warp);
                if (tid == 0)
                    push_all(&s->attnp[rk], make_float4(r4[0], r4[1], r4[2], r4[3]));
            }
            CLUSTER_SYNC();   // g4 + attnp assembled everywhere

            // c/h update, (col, rp) parallel
            {
                float4 pa = s->attnp[0], pb = s->attnp[1],
                       pc = s->attnp[2], pd = s->attnp[3];
                float4 sum4 = make_float4(pa.x + pb.x + pc.x + pd.x,
                                          pa.y + pb.y + pc.y + pd.y,
                                          pa.z + pb.z + pc.z + pd.z,
                                          pa.w + pb.w + pc.w + pd.w);
                float2 ss = reinterpret_cast<const float2*>(&sum4)[rp];
                float ab2v = s->ab2c[l];
                float2 imp = make_float2(sigf(ss.x + ab2v), sigf(ss.y + ab2v));
                float2 gi = reinterpret_cast<const float2*>(&s->g4[col])[rp];
                float2 gf = reinterpret_cast<const float2*>(&s->g4[HID + col])[rp];
                float2 gg = reinterpret_cast<const float2*>(&s->g4[2 * HID + col])[rp];
                float2 go = reinterpret_cast<const float2*>(&s->g4[3 * HID + col])[rp];
                float2 co = reinterpret_cast<const float2*>(&s->c[l][col])[rp];
                float2 cp;
                cp.x = (sigf(gf.x) * co.x + sigf(gi.x) * tanhf_(gg.x)) * imp.x;
                cp.y = (sigf(gf.y) * co.y + sigf(gi.y) * tanhf_(gg.y)) * imp.y;
                float r4[4] = { cp.x, cp.x * cp.x, cp.y, cp.y * cp.y };
                redx<4, 2>(r4, s, tid, lane, warp);
                float sg = s->lnp[l][4][col], sb = s->lnp[l][5][col];
                float2 cn, hv;
                float mu, var, rs;
                mu = r4[0] * invH; var = r4[1] * invH - mu * mu; rs = rsqrtf(var + LN_EPS);
                cn.x = (cp.x - mu) * rs * sg + sb;  hv.x = sigf(go.x) * tanhf_(cn.x);
                mu = r4[2] * invH; var = r4[3] * invH - mu * mu; rs = rsqrtf(var + LN_EPS);
                cn.y = (cp.y - mu) * rs * sg + sb;  hv.y = sigf(go.y) * tanhf_(cn.y);
                reinterpret_cast<float2*>(&s->c[l][col])[rp] = cn;
                reinterpret_cast<float2*>(&s->h[l][col])[rp] = hv;
                reinterpret_cast<float2*>(&s->x[col])[rp]    = hv;
            }
            __syncthreads();

            // residual GEMV1 slice: cols [rk*128,+128) of 512, k=256
            gemv4<32, 16, 16, 2 * HID>(
                p.rw1 + (size_t)l * HID * (2 * HID) + rk * 128,
                s->x, s->part, tid);
            __syncthreads();
            if (tid < 128) {
                float4 v = combine<32, 16>(s->part, tid);
                float bb = s->rb1c[l][rk * 128 + tid];
                v.x = fmaxf(v.x + bb, 0.f); v.y = fmaxf(v.y + bb, 0.f);
                v.z = fmaxf(v.z + bb, 0.f); v.w = fmaxf(v.w + bb, 0.f);
                push_all(&s->t1[rk * 128 + tid], v);
            }
            CLUSTER_SYNC();   // t1 assembled

            // residual GEMV2 slice: cols [rk*64,+64) of 256, k=512
            gemv4<16, 32, 16, HID>(
                p.rw2 + (size_t)l * (2 * HID) * HID + rk * 64,
                s->t1, s->part, tid);
            __syncthreads();
            if (tid < 64) {
                float4 v = combine<16, 32>(s->part, tid);
                int gcol = rk * 64 + tid;
                float bb = s->rb2c[l][gcol];
                float4 xv = s->x[gcol];
                v.x += bb + xv.x; v.y += bb + xv.y;
                v.z += bb + xv.z; v.w += bb + xv.w;
                push_all(&s->gin[gcol], v);
            }
            CLUSTER_SYNC();   // pre-LN vector assembled

            // r-LN + residual
            {
                float2 v = reinterpret_cast<const float2*>(&s->gin[col])[rp];
                float r4[4] = { v.x, v.x * v.x, v.y, v.y * v.y };
                redx<4, 2>(r4, s, tid, lane, warp);
                float rg = s->lnp[l][6][col], rb = s->lnp[l][7][col];
                float2 xo;
                float mu, var, rs;
                mu = r4[0] * invH; var = r4[1] * invH - mu * mu; rs = rsqrtf(var + LN_EPS);
                xo.x = (v.x - mu) * rs * rg + rb + resid.x;
                mu = r4[2] * invH; var = r4[3] * invH - mu * mu; rs = rsqrtf(var + LN_EPS);
                xo.y = (v.y - mu) * rs * rg + rb + resid.y;
                reinterpret_cast<float2*>(&s->x[col])[rp] = xo;
            }
            __syncthreads();
        }

        // ---- output head ----
        gemv4<8, 64, 6, H2>(p.ow1 + rk * 32, s->x, s->part, tid);
        __syncthreads();
        if (tid < 32) {
            float4 v = combine<8, 64>(s->part, tid);
            float bb = s->ob1c[rk * 32 + tid];
            v.x += bb; v.y += bb; v.z += bb; v.w += bb;
            push_all(&s->hd[rk * 32 + tid], v);
        }
        CLUSTER_SYNC();   // hd assembled
        {
            const bool act = (col < H2);
            float2 zv = make_float2(0.f, 0.f);
            if (act) zv = reinterpret_cast<const float2*>(&s->hd[col])[rp];
            float r4[4] = { zv.x, zv.x * zv.x, zv.y, zv.y * zv.y };
            redx<4, 2>(r4, s, tid, lane, warp);
            float r2[2] = { 0.f, 0.f };
            if (act) {
                float og = s->olng[col], ob = s->olnb[col];
                float w2 = s->ow2c[col];
                float mu, var, rs;
                mu = r4[0] * invH2; var = r4[1] * invH2 - mu * mu; rs = rsqrtf(var + LN_EPS);
                r2[0] = fmaxf((zv.x - mu) * rs * og + ob, 0.f) * w2;
                mu = r4[2] * invH2; var = r4[3] * invH2 - mu * mu; rs = rsqrtf(var + LN_EPS);
                r2[1] = fmaxf((zv.y - mu) * rs * og + ob, 0.f) * w2;
            }
            redx<2, 2>(r2, s, tid, lane, warp);
            float ob2v = s->ob2c;
            if (tid == 0) {
                p.out[(size_t)row0 * TT + t]       = r2[0] + ob2v;
                p.out[(size_t)(row0 + 1) * TT + t] = r2[1] + ob2v;
            }
            if (tid == 256) {
                p.out[(size_t)(row0 + 2) * TT + t] = r2[0] + ob2v;
                p.out[(size_t)(row0 + 3) * TT + t] = r2[1] + ob2v;
            }
        }
        __syncthreads();   // protects s->red reuse across loop iterations
    }
}

extern "C" void kernel_launch(void* const* d_in, const int* in_sizes, int n_in,
                              void* d_out, int out_size) {
    Ptrs p;
    p.params     = (const float*)d_in[0];
    p.disp       = (const float*)d_in[1];
    p.embed_w    = (const float*)d_in[2];
    p.embed_b    = (const float*)d_in[3];
    p.embed_g    = (const float*)d_in[4];
    p.embed_beta = (const float*)d_in[5];
    p.skip_w     = (const float*)d_in[6];
    p.skip_b     = (const float*)d_in[7];
    p.gates_w    = (const float*)d_in[8];
    p.gates_b    = (const float*)d_in[9];
    p.inln_g     = (const float*)d_in[10];
    p.inln_b     = (const float*)d_in[11];
    p.hln_g      = (const float*)d_in[12];
    p.hln_b      = (const float*)d_in[13];
    p.sln_g      = (const float*)d_in[14];
    p.sln_b      = (const float*)d_in[15];
    p.aw1        = (const float*)d_in[16];
    p.ab1        = (const float*)d_in[17];
    p.aw2        = (const float*)d_in[18];
    p.ab2        = (const float*)d_in[19];
    p.rw1        = (const float*)d_in[20];
    p.rb1        = (const float*)d_in[21];
    p.rw2        = (const float*)d_in[22];
    p.rb2        = (const float*)d_in[23];
    p.rln_g      = (const float*)d_in[24];
    p.rln_b      = (const float*)d_in[25];
    p.ow1        = (const float*)d_in[26];
    p.ob1        = (const float*)d_in[27];
    p.oln_g      = (const float*)d_in[28];
    p.oln_b      = (const float*)d_in[29];
    p.ow2        = (const float*)d_in[30];
    p.ob2        = (const float*)d_in[31];
    p.out        = (float*)d_out;

    cudaFuncSetAttribute(xlstm_kernel,
                         cudaFuncAttributeMaxDynamicSharedMemorySize,
                         (int)sizeof(Smem));
    xlstm_kernel<<<BB, NT, sizeof(Smem)>>>(p);
}